// round 3
// baseline (speedup 1.0000x reference)
#include <cuda_runtime.h>
#include <math.h>

#define B_ 64
#define C_ 3
#define N_ 512

__global__ void __launch_bounds__(256)
diffeo_kernel(const float* __restrict__ x,
              const float* __restrict__ Fx,
              const float* __restrict__ Fy,
              float* __restrict__ out,
              float scale) {
    __shared__ float gsh[2][8];   // [row][0..3]=gu_i, [row][4..7]=gv_i

    const int tid  = threadIdx.x;
    const int b    = blockIdx.y;
    const int y0   = blockIdx.x * 2;

    const float PI_INV = (float)M_PI / (float)(N_ - 1);

    // 16 threads: fold y-dependence + envelope into per-row coeffs.
    if (tid < 16) {
        const int  i    = tid & 3;           // x-harmonic index
        const int  isV  = (tid >> 2) & 1;
        const int  row  = (tid >> 3) & 1;
        const float* F  = (isV ? Fy : Fx) + b * 16 + i * 4;
        const float py  = (float)(y0 + row) * PI_INV;
        const float ki  = (float)(i + 1);
        float acc = 0.0f;
#pragma unroll
        for (int j = 0; j < 4; j++) {
            float kj = (float)(j + 1);
            float r  = sqrtf(ki * ki + kj * kj);
            float e  = (r < 4.5f) ? (1.0f / r) : 0.0f;
            float sj = __sinf(py * (float)(j + 1));
            acc = fmaf(F[j] * e, sj, acc);
        }
        gsh[row][(isV << 2) | i] = acc;
    }
    __syncthreads();

    const int row = tid >> 7;            // 0 or 1
    const int lt  = tid & 127;           // lane within row
    const int y   = y0 + row;
    const int x0  = lt * 4;

    const float gu0 = gsh[row][0], gu1 = gsh[row][1], gu2 = gsh[row][2], gu3 = gsh[row][3];
    const float gv0 = gsh[row][4], gv1 = gsh[row][5], gv2 = gsh[row][6], gv3 = gsh[row][7];

    const int img_stride = N_ * N_;
    const float* img   = x   + (size_t)b * C_ * img_stride;
    float*       obase = out + (size_t)b * C_ * img_stride + y * N_ + x0;

    // Incremental sin: s(p0 + k*d), d = PI_INV
    const float p0 = (float)x0 * PI_INV;
    float s1 = __sinf(p0);
    float c1 = __cosf(p0);
    const float sd = __sinf(PI_INV);
    const float cd = __cosf(PI_INV);

    const float fy = (float)y;
    float r0[4], r1[4], r2[4];

#pragma unroll
    for (int k = 0; k < 4; k++) {
        const int xi = x0 + k;

        // harmonics from (s1, c1) via double-angle
        const float s2 = 2.0f * s1 * c1;
        const float c2 = fmaf(2.0f * c1, c1, -1.0f);
        const float s3 = fmaf(s1, c2, c1 * s2);
        const float s4 = 2.0f * s2 * c2;

        const float u = fmaf(gu0, s1, fmaf(gu1, s2, fmaf(gu2, s3, gu3 * s4)));
        const float v = fmaf(gv0, s1, fmaf(gv1, s2, fmaf(gv2, s3, gv3 * s4)));

        float xn = fminf(fmaxf((float)xi - scale * u, 0.0f), (float)(N_ - 1));
        float yn = fminf(fmaxf(fy        - scale * v, 0.0f), (float)(N_ - 1));

        const float xff = floorf(xn);
        const float yff = floorf(yn);
        const int   xf  = (int)xff;
        const int   yf  = (int)yff;
        const float xv  = xn - xff;
        const float yv  = yn - yff;

        // ceil == floor+1 clamped; weight is exactly 0 when xn/yn integer,
        // so the substituted in-bounds tap never contributes.
        const int dxB = (xf < N_ - 1) ? 4      : 0;
        const int dyB = (yf < N_ - 1) ? 4 * N_ : 0;

        const float w00 = (1.0f - yv) * (1.0f - xv);
        const float w01 = (1.0f - yv) * xv;
        const float w10 = yv * (1.0f - xv);
        const float w11 = yv * xv;

        const char* a00 = (const char*)img + ((unsigned)(yf * N_ + xf) << 2);
        const char* a01 = a00 + dxB;
        const char* a10 = a00 + dyB;
        const char* a11 = a10 + dxB;

        {
            float t00 = __ldg((const float*)a00);
            float t01 = __ldg((const float*)a01);
            float t10 = __ldg((const float*)a10);
            float t11 = __ldg((const float*)a11);
            r0[k] = fmaf(w00, t00, fmaf(w01, t01, fmaf(w10, t10, w11 * t11)));
        }
        {
            const int cb = img_stride * 4;
            float t00 = __ldg((const float*)(a00 + cb));
            float t01 = __ldg((const float*)(a01 + cb));
            float t10 = __ldg((const float*)(a10 + cb));
            float t11 = __ldg((const float*)(a11 + cb));
            r1[k] = fmaf(w00, t00, fmaf(w01, t01, fmaf(w10, t10, w11 * t11)));
        }
        {
            const int cb = img_stride * 8;
            float t00 = __ldg((const float*)(a00 + cb));
            float t01 = __ldg((const float*)(a01 + cb));
            float t10 = __ldg((const float*)(a10 + cb));
            float t11 = __ldg((const float*)(a11 + cb));
            r2[k] = fmaf(w00, t00, fmaf(w01, t01, fmaf(w10, t10, w11 * t11)));
        }

        // rotate (s1, c1) by d
        const float ns = fmaf(s1, cd,  c1 * sd);
        const float nc = fmaf(c1, cd, -s1 * sd);
        s1 = ns; c1 = nc;
    }

    *(float4*)(obase + 0 * img_stride) = make_float4(r0[0], r0[1], r0[2], r0[3]);
    *(float4*)(obase + 1 * img_stride) = make_float4(r1[0], r1[1], r1[2], r1[3]);
    *(float4*)(obase + 2 * img_stride) = make_float4(r2[0], r2[1], r2[2], r2[3]);
}

extern "C" void kernel_launch(void* const* d_in, const int* in_sizes, int n_in,
                              void* d_out, int out_size) {
    const float* x  = (const float*)d_in[0];
    const float* Fx = (const float*)d_in[1];
    const float* Fy = (const float*)d_in[2];
    float* out = (float*)d_out;

    const double n_d  = (double)N_;
    const double typ  = n_d * sqrt(M_PI * log(4.0)) / 2.0;
    const double T    = 0.01;
    const float scale = (float)(sqrt(T / (typ * typ)) * n_d);

    dim3 block(256);
    dim3 grid(N_ / 2, B_);   // two rows per block
    diffeo_kernel<<<grid, block>>>(x, Fx, Fy, out, scale);
}

// round 4
// speedup vs baseline: 1.2765x; 1.2765x over previous
#include <cuda_runtime.h>
#include <math.h>

#define B_ 64
#define C_ 3
#define N_ 512

__global__ void __launch_bounds__(256)
diffeo_kernel(const float* __restrict__ x,
              const float* __restrict__ Fx,
              const float* __restrict__ Fy,
              float* __restrict__ out,
              float scale) {
    __shared__ float gsh[2][8];   // [row][0..3]=gu_i, [row][4..7]=gv_i

    const int tid = threadIdx.x;
    const int b   = blockIdx.y;
    const int y0  = blockIdx.x * 2;

    const float PI_INV = (float)M_PI / (float)(N_ - 1);

    // 16 threads: fold y-dependence + envelope into per-row coeffs.
    if (tid < 16) {
        const int  i    = tid & 3;           // x-harmonic index
        const int  isV  = (tid >> 2) & 1;
        const int  row  = (tid >> 3) & 1;
        const float* F  = (isV ? Fy : Fx) + b * 16 + i * 4;
        const float py  = (float)(y0 + row) * PI_INV;
        const float ki  = (float)(i + 1);
        float acc = 0.0f;
#pragma unroll
        for (int j = 0; j < 4; j++) {
            float kj = (float)(j + 1);
            float r  = sqrtf(ki * ki + kj * kj);
            float e  = (r < 4.5f) ? (1.0f / r) : 0.0f;
            float sj = __sinf(py * (float)(j + 1));
            acc = fmaf(F[j] * e, sj, acc);
        }
        gsh[row][(isV << 2) | i] = acc;
    }
    __syncthreads();

    const int warp = tid >> 5;
    const int lane = tid & 31;
    const int row  = warp >> 2;          // 0..1  : which row of the pair
    const int seg  = warp & 3;           // 0..3  : 128-px segment within row
    const int y    = y0 + row;
    const int xb   = seg * 128 + lane;   // this thread's base pixel; +32 per k

    const float gu0 = gsh[row][0], gu1 = gsh[row][1], gu2 = gsh[row][2], gu3 = gsh[row][3];
    const float gv0 = gsh[row][4], gv1 = gsh[row][5], gv2 = gsh[row][6], gv3 = gsh[row][7];

    const int img_stride = N_ * N_;
    const float* img  = x   + (size_t)b * C_ * img_stride;
    float*       orow = out + (size_t)b * C_ * img_stride + y * N_;

    // Incremental sin over k: angle step = 32 * PI_INV
    float s1 = __sinf((float)xb * PI_INV);
    float c1 = __cosf((float)xb * PI_INV);
    const float stepA = 32.0f * PI_INV;
    const float sd = __sinf(stepA);
    const float cd = __cosf(stepA);

    const float fy = (float)y;

#pragma unroll
    for (int k = 0; k < 4; k++) {
        const int xi = xb + k * 32;

        // harmonics from (s1, c1) via double-angle
        const float s2 = 2.0f * s1 * c1;
        const float c2 = fmaf(2.0f * c1, c1, -1.0f);
        const float s3 = fmaf(s1, c2, c1 * s2);
        const float s4 = 2.0f * s2 * c2;

        const float u = fmaf(gu0, s1, fmaf(gu1, s2, fmaf(gu2, s3, gu3 * s4)));
        const float v = fmaf(gv0, s1, fmaf(gv1, s2, fmaf(gv2, s3, gv3 * s4)));

        float xn = fminf(fmaxf((float)xi - scale * u, 0.0f), (float)(N_ - 1));
        float yn = fminf(fmaxf(fy        - scale * v, 0.0f), (float)(N_ - 1));

        const float xff = floorf(xn);
        const float yff = floorf(yn);
        const int   xf  = (int)xff;
        const int   yf  = (int)yff;
        const float xv  = xn - xff;
        const float yv  = yn - yff;

        // ceil == floor+1 clamped; weight is exactly 0 when xn/yn integer,
        // so the substituted in-bounds tap never contributes.
        const int dxB = (xf < N_ - 1) ? 4      : 0;
        const int dyB = (yf < N_ - 1) ? 4 * N_ : 0;

        const float w00 = (1.0f - yv) * (1.0f - xv);
        const float w01 = (1.0f - yv) * xv;
        const float w10 = yv * (1.0f - xv);
        const float w11 = yv * xv;

        const char* a00 = (const char*)img + ((unsigned)(yf * N_ + xf) << 2);
        const char* a01 = a00 + dxB;
        const char* a10 = a00 + dyB;
        const char* a11 = a10 + dxB;

#pragma unroll
        for (int c = 0; c < C_; c++) {
            const int cb = c * img_stride * 4;   // byte offset per channel
            float t00 = __ldg((const float*)(a00 + cb));
            float t01 = __ldg((const float*)(a01 + cb));
            float t10 = __ldg((const float*)(a10 + cb));
            float t11 = __ldg((const float*)(a11 + cb));
            float val = fmaf(w00, t00, fmaf(w01, t01, fmaf(w10, t10, w11 * t11)));
            orow[c * img_stride + xi] = val;     // dense 128B store per warp
        }

        // rotate (s1, c1) by 32*d
        const float ns = fmaf(s1, cd,  c1 * sd);
        const float nc = fmaf(c1, cd, -s1 * sd);
        s1 = ns; c1 = nc;
    }
}

extern "C" void kernel_launch(void* const* d_in, const int* in_sizes, int n_in,
                              void* d_out, int out_size) {
    const float* x  = (const float*)d_in[0];
    const float* Fx = (const float*)d_in[1];
    const float* Fy = (const float*)d_in[2];
    float* out = (float*)d_out;

    const double n_d  = (double)N_;
    const double typ  = n_d * sqrt(M_PI * log(4.0)) / 2.0;
    const double T    = 0.01;
    const float scale = (float)(sqrt(T / (typ * typ)) * n_d);

    dim3 block(256);
    dim3 grid(N_ / 2, B_);   // two rows per block
    diffeo_kernel<<<grid, block>>>(x, Fx, Fy, out, scale);
}